// round 5
// baseline (speedup 1.0000x reference)
#include <cuda_runtime.h>
#include <math.h>

#define BB   16
#define TT   3300
#define RNN  512
#define DMEL 80
#define NCTA 128

// ---------------- device scratch (allocation-free) --------------------------
__device__ float g_m1[BB*DMEL*80];
__device__ float g_m2[BB*DMEL*400];
__device__ float g_mu[(size_t)TT*BB*DMEL];      // [n=t*16+b][80]
__device__ float g_wT[512*1536];                // g_wT[d][m] = w_ih[m][d]
__device__ float g_xp[(size_t)TT*BB*1536];      // x_proj rows n
__device__ float g_hs[(size_t)TT*BB*RNN];       // GRU hidden history
__device__ float g_y1[(size_t)TT*BB*RNN];       // fc1 out
__device__ float g_hbuf[2][BB*RNN];             // double-buffered h
__device__ unsigned g_bar;

// ---------------- upsampling ------------------------------------------------
__global__ void up1_k(const float* __restrict__ mels, const float* __restrict__ kern){
    int idx = blockIdx.x*256 + threadIdx.x;
    if (idx >= BB*DMEL*80) return;
    int w = idx % 80, bc = idx / 80;
    float s = 0.f;
#pragma unroll
    for (int i = 0; i < 11; i++){
        int p = w - 5 + i;
        if (p >= 0 && p < 80) s += mels[bc*16 + p/5] * kern[i];
    }
    g_m1[idx] = s;
}
__global__ void up2_k(const float* __restrict__ kern){
    int idx = blockIdx.x*256 + threadIdx.x;
    if (idx >= BB*DMEL*400) return;
    int w = idx % 400, bc = idx / 400;
    float s = 0.f;
#pragma unroll
    for (int i = 0; i < 11; i++){
        int p = w - 5 + i;
        if (p >= 0 && p < 400) s += g_m1[bc*80 + p/5] * kern[i];
    }
    g_m2[idx] = s;
}
// stage 3 fused with crop (INDENT=550) + transpose to [t][b][f]
__global__ void up3_k(const float* __restrict__ kern){
    int idx = blockIdx.x*256 + threadIdx.x;
    if (idx >= TT*BB*DMEL) return;
    int f = idx % 80, r = idx / 80;
    int b = r & 15, t = r >> 4;
    int bc = b*80 + f;
    float s = 0.f;
#pragma unroll
    for (int i = 0; i < 23; i++)
        s += g_m2[bc*400 + (t + 539 + i)/11] * kern[i];
    g_mu[idx] = s;
}
__global__ void wT_k(const float* __restrict__ w_ih){
    int idx = blockIdx.x*256 + threadIdx.x;
    if (idx >= 512*1536) return;
    int d = idx / 1536, m = idx - d*1536;
    g_wT[idx] = w_ih[(size_t)m*592 + d];
}

// ---------------- generic tiled fp32 GEMM -----------------------------------
// C[n][m] = A[n][:K] . W[m][wOff:wOff+K] + bias[m] (+ g_wT[x_n][m] if gather)
// aSel: 0=g_mu 1=g_hs 2=g_y1 ; cSel: 0=g_xp 1=g_y1 2=Cext
// mode: 0 plain, 1 relu, 2 row permuted to (b*TT + t)
__global__ __launch_bounds__(256) void gemm_k(
    int aSel, const float* __restrict__ W, int ldw, int wOff,
    const float* __restrict__ bias, int cSel, float* __restrict__ Cext,
    int M, int K, int mode, int useGather, const int* __restrict__ xIdx)
{
    const float* A = (aSel==0) ? g_mu : (aSel==1) ? g_hs : g_y1;
    float* C = (cSel==0) ? g_xp : (cSel==1) ? g_y1 : Cext;
    __shared__ float sA[16][72];
    __shared__ float sB[16][72];
    __shared__ int   sX[64];
    int n0 = blockIdx.y << 6, m0 = blockIdx.x << 6;
    int tid = threadIdx.x, tx = tid & 15, ty = tid >> 4;
    float acc[4][4];
#pragma unroll
    for (int i = 0; i < 4; i++)
#pragma unroll
        for (int j = 0; j < 4; j++) acc[i][j] = 0.f;

    if (useGather && tid < 64){
        int n = n0 + tid;
        sX[tid] = xIdx[(n & 15)*TT + (n >> 4)];
    }
    for (int k0 = 0; k0 < K; k0 += 16){
        __syncthreads();
#pragma unroll
        for (int i = 0; i < 4; i++){
            int idx = tid + (i << 8);
            int r = idx >> 4, c = idx & 15;
            sA[c][r] = A[(size_t)(n0 + r)*K + k0 + c];
            sB[c][r] = W[(size_t)(m0 + r)*ldw + wOff + k0 + c];
        }
        __syncthreads();
#pragma unroll
        for (int k = 0; k < 16; k++){
            float4 a = *(const float4*)&sA[k][ty << 2];
            float4 b = *(const float4*)&sB[k][tx << 2];
            float av[4] = {a.x, a.y, a.z, a.w};
            float bv[4] = {b.x, b.y, b.z, b.w};
#pragma unroll
            for (int i = 0; i < 4; i++)
#pragma unroll
                for (int j = 0; j < 4; j++) acc[i][j] += av[i]*bv[j];
        }
    }
    float4 bs = *(const float4*)&bias[m0 + (tx << 2)];
    float bb[4] = {bs.x, bs.y, bs.z, bs.w};
#pragma unroll
    for (int i = 0; i < 4; i++){
        int n = n0 + (ty << 2) + i;
        float o[4];
#pragma unroll
        for (int j = 0; j < 4; j++) o[j] = acc[i][j] + bb[j];
        if (useGather){
            const float* wr = &g_wT[(size_t)sX[(ty << 2) + i]*1536 + m0 + (tx << 2)];
#pragma unroll
            for (int j = 0; j < 4; j++) o[j] += wr[j];
        }
        if (mode == 1)
#pragma unroll
            for (int j = 0; j < 4; j++) o[j] = fmaxf(o[j], 0.f);
        size_t row = (mode == 2) ? ((size_t)(n & 15)*TT + (n >> 4)) : (size_t)n;
        float4 ov = make_float4(o[0], o[1], o[2], o[3]);
        *(float4*)&C[row*M + m0 + (tx << 2)] = ov;
    }
}

// ---------------- persistent GRU --------------------------------------------
__global__ void gru_init_k(){
    for (int e = threadIdx.x; e < BB*RNN; e += 256) g_hbuf[0][e] = 0.f;
    if (threadIdx.x == 0) g_bar = 0u;
}

// h-chunk dot: 6 rows x 4 batches over one K-half (256 values, lane covers 8)
#define GRU_HALF(H) { \
    int kq = (H)*64 + lane*2; \
    float4 hv[4][2]; \
    _Pragma("unroll") \
    for (int b = 0; b < 4; b++){ hv[b][0] = hs4[(bg+b)*128 + kq]; hv[b][1] = hs4[(bg+b)*128 + kq + 1]; } \
    _Pragma("unroll") \
    for (int r = 0; r < 6; r++){ \
        float4 w0 = *(const float4*)&w_s[(rbase+r)*512 + kq*4]; \
        float4 w1 = *(const float4*)&w_s[(rbase+r)*512 + kq*4 + 4]; \
        _Pragma("unroll") \
        for (int b = 0; b < 4; b++){ \
            acc[r][b] += w0.x*hv[b][0].x + w0.y*hv[b][0].y + w0.z*hv[b][0].z + w0.w*hv[b][0].w \
                       + w1.x*hv[b][1].x + w1.y*hv[b][1].y + w1.z*hv[b][1].z + w1.w*hv[b][1].w; } } }

__global__ __launch_bounds__(256) void gru_k(const float* __restrict__ w_hh,
                                             const float* __restrict__ b_hh)
{
    extern __shared__ float sm[];
    float* w_s  = sm;                 // 12*512
    float* h_s  = sm + 6144;          // 16*512
    float* hp_s = sm + 6144 + 8192;   // 12*16
    float4* hs4 = (float4*)h_s;
    int tid = threadIdx.x, j0 = blockIdx.x*4;
    int lane = tid & 31, warp = tid >> 5;
    int bg = (warp & 3)*4, rbase = (warp >> 2)*6;
    int gu = tid >> 4, gb = tid & 15;

    for (int i = tid; i < 12*512; i += 256){
        int ri = i >> 9, k = i & 511;
        w_s[i] = w_hh[(size_t)(((ri >> 2)*512) + j0 + (ri & 3))*512 + k];
    }
    float brr = 0.f, bzz = 0.f, bnn = 0.f;
    if (tid < 64){
        brr = b_hh[j0 + gu]; bzz = b_hh[512 + j0 + gu]; bnn = b_hh[1024 + j0 + gu];
    }
    __syncthreads();

    for (int t = 0; t < TT; t++){
        float xr = 0.f, xz = 0.f, xn = 0.f;
        if (tid < 64){
            const float* xp = &g_xp[(size_t)(t*16 + gb)*1536 + j0 + gu];
            xr = __ldg(xp); xz = __ldg(xp + 512); xn = __ldg(xp + 1024);
        }
        const float4* src = (const float4*)g_hbuf[t & 1];
        float4 ra[4], rb[4];
#pragma unroll
        for (int i = 0; i < 4; i++){
            int f = tid + (i << 8); int b = f >> 6, kq = f & 63;
            ra[i] = __ldcg(&src[b*128 + kq]);
            rb[i] = __ldcg(&src[b*128 + 64 + kq]);
        }
        float acc[6][4];
#pragma unroll
        for (int r = 0; r < 6; r++)
#pragma unroll
            for (int b = 0; b < 4; b++) acc[r][b] = 0.f;
#pragma unroll
        for (int i = 0; i < 4; i++){ int f = tid + (i << 8); hs4[(f >> 6)*128 + (f & 63)] = ra[i]; }
        __syncthreads();
        GRU_HALF(0);
#pragma unroll
        for (int i = 0; i < 4; i++){ int f = tid + (i << 8); hs4[(f >> 6)*128 + 64 + (f & 63)] = rb[i]; }
        __syncthreads();
        GRU_HALF(1);
#pragma unroll
        for (int r = 0; r < 6; r++)
#pragma unroll
            for (int b = 0; b < 4; b++){
                float v = acc[r][b];
                v += __shfl_xor_sync(0xffffffffu, v, 16);
                v += __shfl_xor_sync(0xffffffffu, v, 8);
                v += __shfl_xor_sync(0xffffffffu, v, 4);
                v += __shfl_xor_sync(0xffffffffu, v, 2);
                v += __shfl_xor_sync(0xffffffffu, v, 1);
                if (lane == 0) hp_s[(rbase + r)*16 + bg + b] = v;
            }
        __syncthreads();
        if (tid < 64){
            float hr = hp_s[gu*16 + gb] + brr;
            float hz = hp_s[(4 + gu)*16 + gb] + bzz;
            float hn = hp_s[(8 + gu)*16 + gb] + bnn;
            float rg = 1.f/(1.f + expf(-(xr + hr)));
            float zg = 1.f/(1.f + expf(-(xz + hz)));
            float ng = tanhf(xn + rg*hn);
            float hold = h_s[gb*512 + j0 + gu];
            float hnew = (1.f - zg)*ng + zg*hold;
            g_hbuf[(t + 1) & 1][gb*512 + j0 + gu] = hnew;
            g_hs[((size_t)t*16 + gb)*512 + j0 + gu] = hnew;
        }
        __threadfence();
        __syncthreads();
        if (tid == 0){
            atomicAdd(&g_bar, 1u);
            unsigned tgt = (unsigned)(t + 1)*NCTA;
            while (*(volatile unsigned*)&g_bar < tgt) { }
        }
        __syncthreads();
    }
}

// ---------------- launch ----------------------------------------------------
extern "C" void kernel_launch(void* const* d_in, const int* in_sizes, int n_in,
                              void* d_out, int out_size)
{
    const int*   x    = (const int*)  d_in[0];
    const float* mels = (const float*)d_in[1];
    const float* k0   = (const float*)d_in[2];
    const float* k1   = (const float*)d_in[3];
    const float* k2   = (const float*)d_in[4];
    const float* w_ih = (const float*)d_in[5];
    const float* w_hh = (const float*)d_in[6];
    const float* b_ih = (const float*)d_in[7];
    const float* b_hh = (const float*)d_in[8];
    const float* fc1w = (const float*)d_in[9];
    const float* fc1b = (const float*)d_in[10];
    const float* fc2w = (const float*)d_in[11];
    const float* fc2b = (const float*)d_in[12];
    float* out = (float*)d_out;

    cudaFuncSetAttribute(gru_k, cudaFuncAttributeMaxDynamicSharedMemorySize, 58112);

    up1_k<<<400, 256>>>(mels, k0);
    up2_k<<<2000, 256>>>(k1);
    up3_k<<<16500, 256>>>(k2);
    wT_k<<<3072, 256>>>(w_ih);
    // x_proj: rows=52800, M=1536, K=80, + one-hot gather + b_ih
    gemm_k<<<dim3(24, 825), 256>>>(0, w_ih, 592, 512, b_ih, 0, nullptr, 1536, 80, 0, 1, x);
    gru_init_k<<<1, 256>>>();
    gru_k<<<NCTA, 256, 58112>>>(w_hh, b_hh);
    // fc1: relu(g_hs @ fc1_w^T + b)
    gemm_k<<<dim3(8, 825), 256>>>(1, fc1w, 512, 0, fc1b, 1, nullptr, 512, 512, 1, 0, nullptr);
    // fc2: out[b][t][c], permuted rows
    gemm_k<<<dim3(8, 825), 256>>>(2, fc2w, 512, 0, fc2b, 2, out, 512, 512, 2, 0, nullptr);
}

// round 8
// speedup vs baseline: 1.1250x; 1.1250x over previous
#include <cuda_runtime.h>
#include <math.h>

#define BB   16
#define TT   3300
#define RNN  512
#define DMEL 80
#define NCTA 128

// ---------------- device scratch (allocation-free) --------------------------
__device__ float g_m1[BB*DMEL*80];
__device__ float g_m2[BB*DMEL*400];
__device__ float g_mu[(size_t)TT*BB*DMEL];      // [n=t*16+b][80]
__device__ float g_wT[512*1536];                // g_wT[d][m] = w_ih[m][d]
__device__ float g_xp[(size_t)TT*BB*1536];      // x_proj rows n
__device__ float g_hs[(size_t)TT*BB*RNN];       // GRU hidden history
__device__ float g_y1[(size_t)TT*BB*RNN];       // fc1 out
__device__ float g_hbuf[2][BB*RNN];             // double-buffered h
__device__ unsigned g_bar;

// ---------------- upsampling ------------------------------------------------
__global__ void up1_k(const float* __restrict__ mels, const float* __restrict__ kern){
    int idx = blockIdx.x*256 + threadIdx.x;
    if (idx >= BB*DMEL*80) return;
    int w = idx % 80, bc = idx / 80;
    float s = 0.f;
#pragma unroll
    for (int i = 0; i < 11; i++){
        int p = w - 5 + i;
        if (p >= 0 && p < 80) s += mels[bc*16 + p/5] * kern[i];
    }
    g_m1[idx] = s;
}
__global__ void up2_k(const float* __restrict__ kern){
    int idx = blockIdx.x*256 + threadIdx.x;
    if (idx >= BB*DMEL*400) return;
    int w = idx % 400, bc = idx / 400;
    float s = 0.f;
#pragma unroll
    for (int i = 0; i < 11; i++){
        int p = w - 5 + i;
        if (p >= 0 && p < 400) s += g_m1[bc*80 + p/5] * kern[i];
    }
    g_m2[idx] = s;
}
// stage 3 fused with crop (INDENT=550) + transpose to [t][b][f]
__global__ void up3_k(const float* __restrict__ kern){
    int idx = blockIdx.x*256 + threadIdx.x;
    if (idx >= TT*BB*DMEL) return;
    int f = idx % 80, r = idx / 80;
    int b = r & 15, t = r >> 4;
    int bc = b*80 + f;
    float s = 0.f;
#pragma unroll
    for (int i = 0; i < 23; i++)
        s += g_m2[bc*400 + (t + 539 + i)/11] * kern[i];
    g_mu[idx] = s;
}
__global__ void wT_k(const float* __restrict__ w_ih){
    int idx = blockIdx.x*256 + threadIdx.x;
    if (idx >= 512*1536) return;
    int d = idx / 1536, m = idx - d*1536;
    g_wT[idx] = w_ih[(size_t)m*592 + d];
}

// ---------------- generic tiled fp32 GEMM (unchanged, known-good) -----------
__global__ __launch_bounds__(256) void gemm_k(
    int aSel, const float* __restrict__ W, int ldw, int wOff,
    const float* __restrict__ bias, int cSel, float* __restrict__ Cext,
    int M, int K, int mode, int useGather, const int* __restrict__ xIdx)
{
    const float* A = (aSel==0) ? g_mu : (aSel==1) ? g_hs : g_y1;
    float* C = (cSel==0) ? g_xp : (cSel==1) ? g_y1 : Cext;
    __shared__ float sA[16][72];
    __shared__ float sB[16][72];
    __shared__ int   sX[64];
    int n0 = blockIdx.y << 6, m0 = blockIdx.x << 6;
    int tid = threadIdx.x, tx = tid & 15, ty = tid >> 4;
    float acc[4][4];
#pragma unroll
    for (int i = 0; i < 4; i++)
#pragma unroll
        for (int j = 0; j < 4; j++) acc[i][j] = 0.f;

    if (useGather && tid < 64){
        int n = n0 + tid;
        sX[tid] = xIdx[(n & 15)*TT + (n >> 4)];
    }
    for (int k0 = 0; k0 < K; k0 += 16){
        __syncthreads();
#pragma unroll
        for (int i = 0; i < 4; i++){
            int idx = tid + (i << 8);
            int r = idx >> 4, c = idx & 15;
            sA[c][r] = A[(size_t)(n0 + r)*K + k0 + c];
            sB[c][r] = W[(size_t)(m0 + r)*ldw + wOff + k0 + c];
        }
        __syncthreads();
#pragma unroll
        for (int k = 0; k < 16; k++){
            float4 a = *(const float4*)&sA[k][ty << 2];
            float4 b = *(const float4*)&sB[k][tx << 2];
            float av[4] = {a.x, a.y, a.z, a.w};
            float bv[4] = {b.x, b.y, b.z, b.w};
#pragma unroll
            for (int i = 0; i < 4; i++)
#pragma unroll
                for (int j = 0; j < 4; j++) acc[i][j] += av[i]*bv[j];
        }
    }
    float4 bs = *(const float4*)&bias[m0 + (tx << 2)];
    float bb[4] = {bs.x, bs.y, bs.z, bs.w};
#pragma unroll
    for (int i = 0; i < 4; i++){
        int n = n0 + (ty << 2) + i;
        float o[4];
#pragma unroll
        for (int j = 0; j < 4; j++) o[j] = acc[i][j] + bb[j];
        if (useGather){
            const float* wr = &g_wT[(size_t)sX[(ty << 2) + i]*1536 + m0 + (tx << 2)];
#pragma unroll
            for (int j = 0; j < 4; j++) o[j] += wr[j];
        }
        if (mode == 1)
#pragma unroll
            for (int j = 0; j < 4; j++) o[j] = fmaxf(o[j], 0.f);
        size_t row = (mode == 2) ? ((size_t)(n & 15)*TT + (n >> 4)) : (size_t)n;
        float4 ov = make_float4(o[0], o[1], o[2], o[3]);
        *(float4*)&C[row*M + m0 + (tx << 2)] = ov;
    }
}

// ---------------- persistent GRU (register-resident W, f32x2) ---------------
__global__ void gru_init_k(){
    for (int e = threadIdx.x; e < BB*RNN; e += 256) g_hbuf[0][e] = 0.f;
    if (threadIdx.x == 0) g_bar = 0u;
}

__device__ __forceinline__ unsigned long long pk2(unsigned x, unsigned y){
    unsigned long long r;
    asm("mov.b64 %0, {%1, %2};" : "=l"(r) : "r"(x), "r"(y));
    return r;
}

__global__ __launch_bounds__(256) void gru_k(const float* __restrict__ w_hh,
                                             const float* __restrict__ b_hh)
{
    __shared__ float part[2*12*16*8];   // [kh][row][batch][8 partials] = 12KB
    int tid = threadIdx.x, j0 = blockIdx.x*4;
    int lane = tid & 31, warp = tid >> 5;
    int kh = warp & 1, bg = warp >> 1;          // bg in 0..3 (batch group of 4)
    int kbase = kh*256 + lane*8;                // 8 k-floats per lane
    int gu = tid >> 4, gb = tid & 15;           // gate mapping (tid < 64)

    // preload this thread's w_hh slice into registers, packed f32x2
    unsigned long long wp[12][4];
#pragma unroll
    for (int r = 0; r < 12; r++){
        const uint4* p = (const uint4*)&w_hh[(size_t)((r>>2)*512 + j0 + (r&3))*512 + kbase];
        uint4 q0 = p[0], q1 = p[1];
        wp[r][0] = pk2(q0.x, q0.y); wp[r][1] = pk2(q0.z, q0.w);
        wp[r][2] = pk2(q1.x, q1.y); wp[r][3] = pk2(q1.z, q1.w);
    }
    float brr = 0.f, bzz = 0.f, bnn = 0.f, xr = 0.f, xz = 0.f, xn = 0.f;
    if (tid < 64){
        brr = b_hh[j0 + gu]; bzz = b_hh[512 + j0 + gu]; bnn = b_hh[1024 + j0 + gu];
        const float* xp = &g_xp[(size_t)gb*1536 + j0 + gu];   // t = 0
        xr = __ldg(xp); xz = __ldg(xp + 512); xn = __ldg(xp + 1024);
    }

    for (int t = 0; t < TT; t++){
        const float* hb = g_hbuf[t & 1];
        // h slice: 4 batches x 8 k-floats, L2 -> registers, packed
        unsigned long long hp[4][4];
#pragma unroll
        for (int b = 0; b < 4; b++){
            const uint4* p = (const uint4*)&hb[(bg*4 + b)*512 + kbase];
            uint4 q0 = __ldcg(p), q1 = __ldcg(p + 1);
            hp[b][0] = pk2(q0.x, q0.y); hp[b][1] = pk2(q0.z, q0.w);
            hp[b][2] = pk2(q1.x, q1.y); hp[b][3] = pk2(q1.z, q1.w);
        }
        float hold = 0.f;
        if (tid < 64) hold = __ldcg(&hb[gb*512 + j0 + gu]);

        // 12 rows x 4 batches packed dots, reduce fused (keeps live regs low)
#pragma unroll
        for (int r = 0; r < 12; r++)
#pragma unroll
            for (int b = 0; b < 4; b++){
                unsigned long long a2;
                asm("mul.rn.f32x2 %0, %1, %2;"     : "=l"(a2) : "l"(wp[r][0]), "l"(hp[b][0]));
                asm("fma.rn.f32x2 %0, %1, %2, %0;" : "+l"(a2) : "l"(wp[r][1]), "l"(hp[b][1]));
                asm("fma.rn.f32x2 %0, %1, %2, %0;" : "+l"(a2) : "l"(wp[r][2]), "l"(hp[b][2]));
                asm("fma.rn.f32x2 %0, %1, %2, %0;" : "+l"(a2) : "l"(wp[r][3]), "l"(hp[b][3]));
                float lo, hi;
                asm("mov.b64 {%0, %1}, %2;" : "=f"(lo), "=f"(hi) : "l"(a2));
                float v = lo + hi;
                v += __shfl_xor_sync(0xffffffffu, v, 1);
                v += __shfl_xor_sync(0xffffffffu, v, 2);
                if ((lane & 3) == 0)
                    part[kh*1536 + r*128 + (bg*4 + b)*8 + (lane >> 2)] = v;
            }
        __syncthreads();

        if (tid < 64){
            float d[3];
#pragma unroll
            for (int g = 0; g < 3; g++){
                int row = g*4 + gu;
                const float4* p0 = (const float4*)&part[row*128 + gb*8];
                const float4* p1 = (const float4*)&part[1536 + row*128 + gb*8];
                float4 a = p0[0], b4 = p0[1], c = p1[0], e = p1[1];
                d[g] = ((a.x + a.y) + (a.z + a.w)) + ((b4.x + b4.y) + (b4.z + b4.w))
                     + ((c.x + c.y) + (c.z + c.w)) + ((e.x + e.y) + (e.z + e.w));
            }
            float rg = 1.f/(1.f + expf(-(xr + d[0] + brr)));
            float zg = 1.f/(1.f + expf(-(xz + d[1] + bzz)));
            float ng = tanhf(xn + rg*(d[2] + bnn));
            float hnew = (1.f - zg)*ng + zg*hold;
            g_hbuf[(t + 1) & 1][gb*512 + j0 + gu] = hnew;
            g_hs[((size_t)t*16 + gb)*512 + j0 + gu] = hnew;
            // prefetch next step's x_proj (latency hidden behind barrier)
            int tn = (t + 1 < TT) ? t + 1 : t;
            const float* xp = &g_xp[(size_t)(tn*16 + gb)*1536 + j0 + gu];
            xr = __ldg(xp); xz = __ldg(xp + 512); xn = __ldg(xp + 1024);
        }
        __syncthreads();
        if (tid == 0){
            __threadfence();                       // gpu-scope release (1 thread)
            atomicAdd(&g_bar, 1u);
            unsigned tgt = (unsigned)(t + 1)*NCTA, v;
            do {
                asm volatile("ld.acquire.gpu.global.u32 %0, [%1];"
                             : "=r"(v) : "l"(&g_bar) : "memory");
                if (v >= tgt) break;
                __nanosleep(64);
            } while (true);
        }
        __syncthreads();
    }
}

// ---------------- launch ----------------------------------------------------
extern "C" void kernel_launch(void* const* d_in, const int* in_sizes, int n_in,
                              void* d_out, int out_size)
{
    const int*   x    = (const int*)  d_in[0];
    const float* mels = (const float*)d_in[1];
    const float* k0   = (const float*)d_in[2];
    const float* k1   = (const float*)d_in[3];
    const float* k2   = (const float*)d_in[4];
    const float* w_ih = (const float*)d_in[5];
    const float* w_hh = (const float*)d_in[6];
    const float* b_ih = (const float*)d_in[7];
    const float* b_hh = (const float*)d_in[8];
    const float* fc1w = (const float*)d_in[9];
    const float* fc1b = (const float*)d_in[10];
    const float* fc2w = (const float*)d_in[11];
    const float* fc2b = (const float*)d_in[12];
    float* out = (float*)d_out;

    up1_k<<<400, 256>>>(mels, k0);
    up2_k<<<2000, 256>>>(k1);
    up3_k<<<16500, 256>>>(k2);
    wT_k<<<3072, 256>>>(w_ih);
    // x_proj: rows=52800, M=1536, K=80, + one-hot gather + b_ih
    gemm_k<<<dim3(24, 825), 256>>>(0, w_ih, 592, 512, b_ih, 0, nullptr, 1536, 80, 0, 1, x);
    gru_init_k<<<1, 256>>>();
    gru_k<<<NCTA, 256>>>(w_hh, b_hh);
    // fc1: relu(g_hs @ fc1_w^T + b)
    gemm_k<<<dim3(8, 825), 256>>>(1, fc1w, 512, 0, fc1b, 1, nullptr, 512, 512, 1, 0, nullptr);
    // fc2: out[b][t][c], permuted rows
    gemm_k<<<dim3(8, 825), 256>>>(2, fc2w, 512, 0, fc2b, 2, out, 512, 512, 2, 0, nullptr);
}